// round 14
// baseline (speedup 1.0000x reference)
#include <cuda_runtime.h>
#include <cuda_fp16.h>
#include <cstdint>

// VariationalLinear: out[1024,4096] = x @ (mu + eps_w*sigma)^T + (b_mu + eps_b*b_sigma)
// R14 = R13 with 2 CTAs/SM: BM=128, 256 threads/CTA, grid (8,32)=256 CTAs (single
// wave at occ 2), one barrier per chunk (the redundant post-MMA sync removed).
// prep_w / prep_x unchanged (prep_w measured 81.5% of DRAM roofline).

static constexpr int MDIM = 1024, NDIM = 4096, KDIM = 4096;
static constexpr int BM = 128, BN = 128, BK = 64;
static constexpr int KCH = KDIM / BK;       // 64
static constexpr int THREADS = 256;
static constexpr int STAGES = 3;
static constexpr int ROWB = 144;            // 64 halves (128B) + 16B pad
static constexpr int ASTG = BM * ROWB;      // 18432
static constexpr int BSTG = BN * ROWB;      // 18432
static constexpr int STG = ASTG + BSTG;     // 36864 per stage
static constexpr int OFF_A = 512;           // [0,512) fused bias; A at stage base
static constexpr int OFF_B = OFF_A + ASTG;
static constexpr int SMEM_TOTAL = 512 + STAGES * STG;   // 111104 (x2 = 222KB/SM)

__device__ __align__(16) __half g_xh[MDIM * KDIM];    // fp16 x (8.4 MB)
__device__ __align__(16) __half g_wh[NDIM * KDIM];    // fp16 fused W (33.5 MB)

__device__ __forceinline__ uint32_t smem_u32(const void* p) {
    uint32_t a;
    asm("{ .reg .u64 t; cvta.to.shared.u64 t, %1; cvt.u32.u64 %0, t; }" : "=r"(a) : "l"(p));
    return a;
}
__device__ __forceinline__ void cp16(uint32_t dst, const void* src) {
    asm volatile("cp.async.cg.shared.global [%0], [%1], 16;" :: "r"(dst), "l"(src));
}
#define CP_COMMIT() asm volatile("cp.async.commit_group;" ::: "memory")
#define CP_WAIT1()  asm volatile("cp.async.wait_group 1;" ::: "memory")

#define LDSM4(r, addr) asm volatile( \
    "ldmatrix.sync.aligned.m8n8.x4.shared.b16 {%0,%1,%2,%3}, [%4];" \
    : "=r"((r)[0]), "=r"((r)[1]), "=r"((r)[2]), "=r"((r)[3]) : "r"(addr))

#define MMA16(ac, a, b0, b1) asm volatile( \
    "mma.sync.aligned.m16n8k16.row.col.f32.f16.f16.f32 " \
    "{%0,%1,%2,%3}, {%4,%5,%6,%7}, {%8,%9}, {%0,%1,%2,%3};" \
    : "+f"((ac)[0]), "+f"((ac)[1]), "+f"((ac)[2]), "+f"((ac)[3]) \
    : "r"((a)[0]), "r"((a)[1]), "r"((a)[2]), "r"((a)[3]), "r"(b0), "r"(b1))

// ---------------- prep kernels (measured near DRAM roofline) ----------------
__global__ void __launch_bounds__(256) prep_x(const float* __restrict__ x) {
    int i = blockIdx.x * 256 + threadIdx.x;              // 8 floats / thread
    const float4* src = (const float4*)x;
    float4 v0 = __ldcs(src + 2 * i), v1 = __ldcs(src + 2 * i + 1);
    __half2 h[4];
    h[0] = __floats2half2_rn(v0.x, v0.y);  h[1] = __floats2half2_rn(v0.z, v0.w);
    h[2] = __floats2half2_rn(v1.x, v1.y);  h[3] = __floats2half2_rn(v1.z, v1.w);
    ((uint4*)g_xh)[i] = *(uint4*)h;
}
__global__ void __launch_bounds__(256) prep_w(const float* __restrict__ mu,
                                              const float* __restrict__ sg,
                                              const float* __restrict__ ep) {
    int i = blockIdx.x * 256 + threadIdx.x;              // 8 floats / thread
    const float4* M = (const float4*)mu;
    const float4* S = (const float4*)sg;
    const float4* E = (const float4*)ep;
    float4 m0 = __ldcs(M + 2 * i), m1 = __ldcs(M + 2 * i + 1);
    float4 s0 = __ldcs(S + 2 * i), s1 = __ldcs(S + 2 * i + 1);
    float4 e0 = __ldcs(E + 2 * i), e1 = __ldcs(E + 2 * i + 1);
    __half2 h[4];
    h[0] = __floats2half2_rn(fmaf(e0.x, s0.x, m0.x), fmaf(e0.y, s0.y, m0.y));
    h[1] = __floats2half2_rn(fmaf(e0.z, s0.z, m0.z), fmaf(e0.w, s0.w, m0.w));
    h[2] = __floats2half2_rn(fmaf(e1.x, s1.x, m1.x), fmaf(e1.y, s1.y, m1.y));
    h[3] = __floats2half2_rn(fmaf(e1.z, s1.z, m1.z), fmaf(e1.w, s1.w, m1.w));
    ((uint4*)g_wh)[i] = *(uint4*)h;
}

// ---------------- fp16 GEMM, 3-stage pipeline, 2 CTAs/SM ----------------
__global__ void __launch_bounds__(THREADS, 2)
vlin_gemm(const float* __restrict__ bmu, const float* __restrict__ bsig,
          const float* __restrict__ eb,  float* __restrict__ out) {
    extern __shared__ char smem[];
    const uint32_t sb = smem_u32(smem);
    const int tid = threadIdx.x, wid = tid >> 5, lid = tid & 31;
    const int wm = wid >> 2, wn = wid & 3;               // 2(m) x 4(n) warps
    const int g = lid >> 2, tg = lid & 3;
    const int m0 = blockIdx.x * BM, n0 = blockIdx.y * BN;

    if (tid < BN)
        ((float*)smem)[tid] = fmaf(eb[n0 + tid], bsig[n0 + tid], bmu[n0 + tid]);

    // cp.async mapping: 2 threads/row, each 4x16B (64B half-row); A and B same shape
    const int aR = tid >> 1, aC = (tid & 1) * 32;        // halves
    const __half* aSrc = g_xh + (size_t)(m0 + aR) * KDIM + aC;
    const __half* bSrc = g_wh + (size_t)(n0 + aR) * KDIM + aC;
    const uint32_t aDst = sb + OFF_A + aR * ROWB + aC * 2;
    const uint32_t bDst = sb + OFF_B + aR * ROWB + aC * 2;

    // ldmatrix lane addresses
    const int l15 = lid & 15, lHi = lid >> 4;
    const uint32_t aBase = sb + OFF_A + (wm * 64 + l15) * ROWB + lHi * 16;
    const uint32_t bBase = sb + OFF_B + (wn * 32 + l15) * ROWB + lHi * 16;

    float acc[4][4][4];
    #pragma unroll
    for (int mt = 0; mt < 4; mt++)
        #pragma unroll
        for (int nt = 0; nt < 4; nt++)
            #pragma unroll
            for (int q = 0; q < 4; q++) acc[mt][nt][q] = 0.f;

    // prologue: chunks 0,1 -> stages 0,1 (one commit group each)
    #pragma unroll
    for (int c = 0; c < 2; c++) {
        const uint32_t so = c * STG;
        const __half* as = aSrc + c * BK;
        const __half* bs = bSrc + c * BK;
        #pragma unroll
        for (int j = 0; j < 4; j++) cp16(aDst + so + j * 16, as + j * 8);
        #pragma unroll
        for (int j = 0; j < 4; j++) cp16(bDst + so + j * 16, bs + j * 8);
        CP_COMMIT();
    }

    int s = 0;
    #pragma unroll 1
    for (int i = 0; i < KCH; i++) {
        CP_WAIT1();                              // chunk i's group complete
        __syncthreads();                         // visible to all; frees stage (s+2)%3

        if (i + 2 < KCH) {                       // prefetch chunk i+2 -> stage (s+2)%3
            const int ps = (s + 2 >= STAGES) ? s + 2 - STAGES : s + 2;
            const uint32_t so = ps * STG;
            const __half* as = aSrc + (i + 2) * BK;
            const __half* bs = bSrc + (i + 2) * BK;
            #pragma unroll
            for (int j = 0; j < 4; j++) cp16(aDst + so + j * 16, as + j * 8);
            #pragma unroll
            for (int j = 0; j < 4; j++) cp16(bDst + so + j * 16, bs + j * 8);
        }
        CP_COMMIT();                             // exactly one group per iteration

        const uint32_t aS = aBase + s * STG;
        const uint32_t bS = bBase + s * STG;
        #pragma unroll
        for (int ks = 0; ks < 4; ks++) {         // 4 k-steps of 16
            uint32_t a[4][4], b[2][4];
            #pragma unroll
            for (int mt = 0; mt < 4; mt++) LDSM4(a[mt], aS + mt * 16 * ROWB + ks * 32);
            #pragma unroll
            for (int np = 0; np < 2; np++) LDSM4(b[np], bS + np * 16 * ROWB + ks * 32);
            #pragma unroll
            for (int mt = 0; mt < 4; mt++) {
                MMA16(acc[mt][0], a[mt], b[0][0], b[0][2]);
                MMA16(acc[mt][1], a[mt], b[0][1], b[0][3]);
                MMA16(acc[mt][2], a[mt], b[1][0], b[1][2]);
                MMA16(acc[mt][3], a[mt], b[1][1], b[1][3]);
            }
        }
        s = (s + 1 == STAGES) ? 0 : s + 1;
    }

    // epilogue: acc + bias -> GMEM
    const float* bias_s = (const float*)smem;
    #pragma unroll
    for (int mt = 0; mt < 4; mt++) {
        #pragma unroll
        for (int nt = 0; nt < 4; nt++) {
            const int bc = wn * 32 + nt * 8 + 2 * tg;
            const int R0 = m0 + wm * 64 + mt * 16 + g;
            float2 v0 = { acc[mt][nt][0] + bias_s[bc], acc[mt][nt][1] + bias_s[bc + 1] };
            float2 v1 = { acc[mt][nt][2] + bias_s[bc], acc[mt][nt][3] + bias_s[bc + 1] };
            *(float2*)(out + (size_t)R0 * NDIM + n0 + bc) = v0;
            *(float2*)(out + (size_t)(R0 + 8) * NDIM + n0 + bc) = v1;
        }
    }
}

extern "C" void kernel_launch(void* const* d_in, const int* in_sizes, int n_in,
                              void* d_out, int out_size) {
    (void)in_sizes; (void)n_in; (void)out_size;
    cudaFuncSetAttribute(vlin_gemm, cudaFuncAttributeMaxDynamicSharedMemorySize, SMEM_TOTAL);

    // inputs: x, weight_mu, weight_sigma, bias_mu, bias_sigma, eps_w, eps_b
    prep_w<<<(NDIM * KDIM / 8) / 256, 256>>>((const float*)d_in[1],
                                             (const float*)d_in[2],
                                             (const float*)d_in[5]);
    prep_x<<<(MDIM * KDIM / 8) / 256, 256>>>((const float*)d_in[0]);
    dim3 grid(MDIM / BM, NDIM / BN);   // (8, 32) = 256 CTAs, single wave at occ 2
    vlin_gemm<<<grid, THREADS, SMEM_TOTAL>>>(
        (const float*)d_in[3], (const float*)d_in[4], (const float*)d_in[6],
        (float*)d_out);
}

// round 15
// speedup vs baseline: 1.1005x; 1.1005x over previous
#include <cuda_runtime.h>
#include <cuda_fp16.h>
#include <cstdint>

// VariationalLinear: out[1024,4096] = x @ (mu + eps_w*sigma)^T + (b_mu + eps_b*b_sigma)
// R15 = R13 (best: prep_x + prep_w + pure fp16 GEMM, BM=256/BN=128/BK=64, 512 thr)
// with 4 SMEM stages and TWO chunks per barrier interval: half the wait/__syncthreads
// events, 4096-cyc tensor runs between barriers, one cp.async group per interval
// committed a full interval before consumption (wait_group 0 ~free).

static constexpr int MDIM = 1024, NDIM = 4096, KDIM = 4096;
static constexpr int BM = 256, BN = 128, BK = 64;
static constexpr int KCH = KDIM / BK;       // 64 chunks -> 32 intervals
static constexpr int THREADS = 512;
static constexpr int STAGES = 4;            // chunk c lives in stage c & 3
static constexpr int ROWB = 144;            // 64 halves (128B) + 16B pad
static constexpr int ASTG = BM * ROWB;      // 36864
static constexpr int BSTG = BN * ROWB;      // 18432
static constexpr int STG = ASTG + BSTG;     // 55296 per stage
static constexpr int OFF_A = 512;           // [0,512) fused bias; A at stage base
static constexpr int OFF_B = OFF_A + ASTG;
static constexpr int SMEM_TOTAL = 512 + STAGES * STG;   // 221696

__device__ __align__(16) __half g_xh[MDIM * KDIM];    // fp16 x (8.4 MB)
__device__ __align__(16) __half g_wh[NDIM * KDIM];    // fp16 fused W (33.5 MB)

__device__ __forceinline__ uint32_t smem_u32(const void* p) {
    uint32_t a;
    asm("{ .reg .u64 t; cvta.to.shared.u64 t, %1; cvt.u32.u64 %0, t; }" : "=r"(a) : "l"(p));
    return a;
}
__device__ __forceinline__ void cp16(uint32_t dst, const void* src) {
    asm volatile("cp.async.cg.shared.global [%0], [%1], 16;" :: "r"(dst), "l"(src));
}
#define CP_COMMIT() asm volatile("cp.async.commit_group;" ::: "memory")
#define CP_WAIT0()  asm volatile("cp.async.wait_group 0;" ::: "memory")

#define LDSM4(r, addr) asm volatile( \
    "ldmatrix.sync.aligned.m8n8.x4.shared.b16 {%0,%1,%2,%3}, [%4];" \
    : "=r"((r)[0]), "=r"((r)[1]), "=r"((r)[2]), "=r"((r)[3]) : "r"(addr))

#define MMA16(ac, a, b0, b1) asm volatile( \
    "mma.sync.aligned.m16n8k16.row.col.f32.f16.f16.f32 " \
    "{%0,%1,%2,%3}, {%4,%5,%6,%7}, {%8,%9}, {%0,%1,%2,%3};" \
    : "+f"((ac)[0]), "+f"((ac)[1]), "+f"((ac)[2]), "+f"((ac)[3]) \
    : "r"((a)[0]), "r"((a)[1]), "r"((a)[2]), "r"((a)[3]), "r"(b0), "r"(b1))

// ---------------- prep kernels (measured ~80% of DRAM roofline) ----------------
__global__ void __launch_bounds__(256) prep_x(const float* __restrict__ x) {
    int i = blockIdx.x * 256 + threadIdx.x;              // 8 floats / thread
    const float4* src = (const float4*)x;
    float4 v0 = __ldcs(src + 2 * i), v1 = __ldcs(src + 2 * i + 1);
    __half2 h[4];
    h[0] = __floats2half2_rn(v0.x, v0.y);  h[1] = __floats2half2_rn(v0.z, v0.w);
    h[2] = __floats2half2_rn(v1.x, v1.y);  h[3] = __floats2half2_rn(v1.z, v1.w);
    ((uint4*)g_xh)[i] = *(uint4*)h;
}
__global__ void __launch_bounds__(256) prep_w(const float* __restrict__ mu,
                                              const float* __restrict__ sg,
                                              const float* __restrict__ ep) {
    int i = blockIdx.x * 256 + threadIdx.x;              // 8 floats / thread
    const float4* M = (const float4*)mu;
    const float4* S = (const float4*)sg;
    const float4* E = (const float4*)ep;
    float4 m0 = __ldcs(M + 2 * i), m1 = __ldcs(M + 2 * i + 1);
    float4 s0 = __ldcs(S + 2 * i), s1 = __ldcs(S + 2 * i + 1);
    float4 e0 = __ldcs(E + 2 * i), e1 = __ldcs(E + 2 * i + 1);
    __half2 h[4];
    h[0] = __floats2half2_rn(fmaf(e0.x, s0.x, m0.x), fmaf(e0.y, s0.y, m0.y));
    h[1] = __floats2half2_rn(fmaf(e0.z, s0.z, m0.z), fmaf(e0.w, s0.w, m0.w));
    h[2] = __floats2half2_rn(fmaf(e1.x, s1.x, m1.x), fmaf(e1.y, s1.y, m1.y));
    h[3] = __floats2half2_rn(fmaf(e1.z, s1.z, m1.z), fmaf(e1.w, s1.w, m1.w));
    ((uint4*)g_wh)[i] = *(uint4*)h;
}

// ---------------- pure fp16 GEMM, 4 stages, 2 chunks per barrier ----------------
__global__ void __launch_bounds__(THREADS, 1)
vlin_gemm(const float* __restrict__ bmu, const float* __restrict__ bsig,
          const float* __restrict__ eb,  float* __restrict__ out) {
    extern __shared__ char smem[];
    const uint32_t sb = smem_u32(smem);
    const int tid = threadIdx.x, wid = tid >> 5, lid = tid & 31;
    const int wm = wid >> 2, wn = wid & 3;               // 4(m) x 4(n) warps
    const int g = lid >> 2, tg = lid & 3;
    const int m0 = blockIdx.x * BM, n0 = blockIdx.y * BN;

    if (tid < BN)
        ((float*)smem)[tid] = fmaf(eb[n0 + tid], bsig[n0 + tid], bmu[n0 + tid]);

    // cp.async mapping: A 4x16B/thread (row tid>>1), B 2x16B/thread (row tid>>2)
    const int aR = tid >> 1, aC = (tid & 1) * 32;        // halves
    const int bR = tid >> 2, bC = (tid & 3) * 16;
    const __half* aSrc = g_xh + (size_t)(m0 + aR) * KDIM + aC;
    const __half* bSrc = g_wh + (size_t)(n0 + bR) * KDIM + bC;
    const uint32_t aDst = sb + OFF_A + aR * ROWB + aC * 2;
    const uint32_t bDst = sb + OFF_B + bR * ROWB + bC * 2;

    // ldmatrix lane addresses
    const int l15 = lid & 15, lHi = lid >> 4;
    const uint32_t aBase = sb + OFF_A + (wm * 64 + l15) * ROWB + lHi * 16;
    const uint32_t bBase = sb + OFF_B + (wn * 32 + l15) * ROWB + lHi * 16;

    float acc[4][4][4];
    #pragma unroll
    for (int mt = 0; mt < 4; mt++)
        #pragma unroll
        for (int nt = 0; nt < 4; nt++)
            #pragma unroll
            for (int q = 0; q < 4; q++) acc[mt][nt][q] = 0.f;

    // prologue: chunks 0,1 -> stages 0,1 as ONE group
    #pragma unroll
    for (int c = 0; c < 2; c++) {
        const uint32_t so = c * STG;
        const __half* as = aSrc + c * BK;
        const __half* bs = bSrc + c * BK;
        #pragma unroll
        for (int j = 0; j < 4; j++) cp16(aDst + so + j * 16, as + j * 8);
        #pragma unroll
        for (int j = 0; j < 2; j++) cp16(bDst + so + j * 16, bs + j * 8);
    }
    CP_COMMIT();

    #pragma unroll 1
    for (int iv = 0; iv < KCH / 2; iv++) {       // 32 intervals of 2 chunks
        const int c0 = 2 * iv;
        const int s0 = c0 & 3;                   // 0 or 2; s1 = s0 + 1
        CP_WAIT0();                              // chunks c0, c0+1 resident
        __syncthreads();                         // all warps past interval iv-1

        if (c0 + 2 < KCH) {                      // prefetch next interval's chunks
            #pragma unroll
            for (int c = 0; c < 2; c++) {
                const int ch = c0 + 2 + c;
                const uint32_t so = (uint32_t)(ch & 3) * STG;
                const __half* as = aSrc + ch * BK;
                const __half* bs = bSrc + ch * BK;
                #pragma unroll
                for (int j = 0; j < 4; j++) cp16(aDst + so + j * 16, as + j * 8);
                #pragma unroll
                for (int j = 0; j < 2; j++) cp16(bDst + so + j * 16, bs + j * 8);
            }
        }
        CP_COMMIT();                             // one group per interval

        #pragma unroll
        for (int half = 0; half < 2; half++) {   // compute chunks c0, c0+1
            const uint32_t so = (uint32_t)(s0 + half) * STG;
            const uint32_t aS = aBase + so;
            const uint32_t bS = bBase + so;
            #pragma unroll
            for (int ks = 0; ks < 4; ks++) {     // 4 k-steps of 16
                uint32_t a[4][4], b[2][4];
                #pragma unroll
                for (int mt = 0; mt < 4; mt++) LDSM4(a[mt], aS + mt * 16 * ROWB + ks * 32);
                #pragma unroll
                for (int np = 0; np < 2; np++) LDSM4(b[np], bS + np * 16 * ROWB + ks * 32);
                #pragma unroll
                for (int mt = 0; mt < 4; mt++) {
                    MMA16(acc[mt][0], a[mt], b[0][0], b[0][2]);
                    MMA16(acc[mt][1], a[mt], b[0][1], b[0][3]);
                    MMA16(acc[mt][2], a[mt], b[1][0], b[1][2]);
                    MMA16(acc[mt][3], a[mt], b[1][1], b[1][3]);
                }
            }
        }
    }

    // epilogue: acc + bias -> GMEM
    const float* bias_s = (const float*)smem;
    #pragma unroll
    for (int mt = 0; mt < 4; mt++) {
        #pragma unroll
        for (int nt = 0; nt < 4; nt++) {
            const int bc = wn * 32 + nt * 8 + 2 * tg;
            const int R0 = m0 + wm * 64 + mt * 16 + g;
            float2 v0 = { acc[mt][nt][0] + bias_s[bc], acc[mt][nt][1] + bias_s[bc + 1] };
            float2 v1 = { acc[mt][nt][2] + bias_s[bc], acc[mt][nt][3] + bias_s[bc + 1] };
            *(float2*)(out + (size_t)R0 * NDIM + n0 + bc) = v0;
            *(float2*)(out + (size_t)(R0 + 8) * NDIM + n0 + bc) = v1;
        }
    }
}

extern "C" void kernel_launch(void* const* d_in, const int* in_sizes, int n_in,
                              void* d_out, int out_size) {
    (void)in_sizes; (void)n_in; (void)out_size;
    cudaFuncSetAttribute(vlin_gemm, cudaFuncAttributeMaxDynamicSharedMemorySize, SMEM_TOTAL);

    // inputs: x, weight_mu, weight_sigma, bias_mu, bias_sigma, eps_w, eps_b
    prep_w<<<(NDIM * KDIM / 8) / 256, 256>>>((const float*)d_in[1],
                                             (const float*)d_in[2],
                                             (const float*)d_in[5]);
    prep_x<<<(MDIM * KDIM / 8) / 256, 256>>>((const float*)d_in[0]);
    dim3 grid(MDIM / BM, NDIM / BN);   // (4, 32) = 128 CTAs
    vlin_gemm<<<grid, THREADS, SMEM_TOTAL>>>(
        (const float*)d_in[3], (const float*)d_in[4], (const float*)d_in[6],
        (float*)d_out);
}